// round 6
// baseline (speedup 1.0000x reference)
#include <cuda_runtime.h>
#include <cuda_fp16.h>
#include <mma.h>
#include <math.h>

using namespace nvcuda;

#define T_SEQ 80
#define BATCH 128
#define EMB   100
#define KPAD  128
#define UNITS 2048
#define G3    6144

// ---------------- device scratch (allocation-free) ----------------
__device__ __half g_Bp0[(size_t)UNITS * G3];          // r0 packed [64][2048][96]
__device__ __half g_Bp1[(size_t)UNITS * G3];          // r1 packed [64][2048][96]
__device__ __half g_Bp2[(size_t)UNITS * G3];          // k1 packed [128][2048][48]
__device__ __half g_k0h[(size_t)KPAD * G3];           // k0 fp16, K padded to 128
__device__ __half g_xh [(size_t)T_SEQ * BATCH * KPAD];// gathered embeddings fp16
__device__ __half g_gi0h[(size_t)T_SEQ * BATCH * G3]; // precomputed input proj, fp16
__device__ float  g_gh1[(size_t)BATCH * G3];          // raw h1_prev @ r1 per step
__device__ float  g_h0f[2][(size_t)BATCH * UNITS];
__device__ float  g_h1f[2][(size_t)BATCH * UNITS];
__device__ __half g_h0h[2][(size_t)BATCH * UNITS];
__device__ __half g_h1h[2][(size_t)BATCH * UNITS];

// ---------------- prep kernels ----------------
__global__ void pad_k0h(const float* __restrict__ k0) {
    int idx = blockIdx.x * blockDim.x + threadIdx.x;
    if (idx >= KPAD * G3) return;
    int k = idx / G3;
    g_k0h[idx] = (k < EMB) ? __float2half(k0[idx]) : __half(0);
}

__global__ void gather_embed(const int* __restrict__ tokens, const float* __restrict__ emb) {
    int idx = blockIdx.x * blockDim.x + threadIdx.x;
    if (idx >= T_SEQ * BATCH * KPAD) return;
    int e  = idx & (KPAD - 1);
    int tb = idx >> 7;
    int t  = tb >> 7;          // BATCH == 128
    int b  = tb & 127;
    float v = 0.f;
    if (e < EMB) {
        int tok = tokens[b * T_SEQ + t];
        v = emb[(size_t)tok * EMB + e];
    }
    g_xh[idx] = __float2half(v);
}

// gate-interleave pack: out[u][k][g*BNU+c] = W[k][g*2048 + u*BNU + c]
template<int BNU>
__global__ void pack_gates(const float* __restrict__ W, int which) {
    __half* out = (BNU == 16) ? g_Bp2 : (which ? g_Bp1 : g_Bp0);
    int idx = blockIdx.x * blockDim.x + threadIdx.x;
    if (idx >= UNITS * G3) return;
    const int BNW = 3 * BNU;
    int u   = idx / (UNITS * BNW);
    int r   = idx % (UNITS * BNW);
    int k   = r / BNW;
    int col = r % BNW;
    int g   = col / BNU, c = col % BNU;
    out[idx] = __float2half(W[(size_t)k * G3 + g * UNITS + u * BNU + c]);
}

__global__ void zero_h() {
    int idx = blockIdx.x * blockDim.x + threadIdx.x;
    if (idx >= BATCH * UNITS) return;
    g_h0f[0][idx] = 0.f; g_h1f[0][idx] = 0.f;
    g_h0h[0][idx] = __half(0); g_h1h[0][idx] = __half(0);
}

// ---------------- fused fp16 tensor-core GEMM ----------------
// MODE 0: z=0: gh0 = h0@r0 fused layer-0 combine -> h0' ; z=1: gh1 = h1@r1 raw
// MODE 2: gi1 = h0'@k1 fused layer-1 combine -> h1'
// MODE 3: gi0 = x@k0 for all timesteps (one-time)

__device__ __forceinline__ void cpa16(void* s, const void* g) {
    unsigned sa = (unsigned)__cvta_generic_to_shared(s);
    asm volatile("cp.async.cg.shared.global [%0], [%1], 16;" :: "r"(sa), "l"(g));
}

#define N_STAGE 4

template<int BN> struct SmemT {
    union {
        struct { __half As[N_STAGE][128][40]; __half Bs[N_STAGE][32][BN + 8]; } s;
        float Cs[128][BN];
    } u;
};

template<int MODE>
__global__ __launch_bounds__(256)
void gk(int t, int p, const float* __restrict__ bias) {
    constexpr int BN  = (MODE == 2) ? 48 : 96;
    constexpr int BNU = BN / 3;
    constexpr int K   = (MODE == 3) ? KPAD : UNITS;
    constexpr int NK  = K / 32;
    constexpr int WNG = (BN == 96) ? 2 : 1;
    constexpr int FM  = (BN == 96) ? 2 : 1;
    constexpr int FN  = 3;

    const int u = blockIdx.x;
    const int z = (MODE == 0) ? blockIdx.z : 0;

    const __half* A;
    const __half* B;
    const __half* gi = g_gi0h + (size_t)t * BATCH * G3;
    const float*  hprev;
    float*  hn_f = nullptr;
    __half* hn_h = nullptr;

    if (MODE == 0) {
        A = z ? g_h1h[p] : g_h0h[p];
        B = z ? g_Bp1 : g_Bp0;
        hprev = g_h0f[p]; hn_f = g_h0f[p ^ 1]; hn_h = g_h0h[p ^ 1];
    } else if (MODE == 2) {
        A = g_h0h[p ^ 1];
        B = g_Bp2;
        hprev = g_h1f[p]; hn_f = g_h1f[p ^ 1]; hn_h = g_h1h[p ^ 1];
    } else {
        A = g_xh; B = g_k0h; hprev = nullptr;
    }

    extern __shared__ char smraw[];
    SmemT<BN>& sm = *reinterpret_cast<SmemT<BN>*>(smraw);

    const int tid = threadIdx.x;
    const size_t aRow0 = (MODE == 3) ? (size_t)blockIdx.y * 128 : 0;

#if __CUDA_ARCH__ >= 900
    if (MODE == 0 || MODE == 2) cudaGridDependencySynchronize();
#endif

    auto loadStage = [&](int st, int kb) {
        #pragma unroll
        for (int r = 0; r < 2; r++) {
            int i = tid + r * 256;
            int row = i >> 2, co = (i & 3) * 8;
            cpa16(&sm.u.s.As[st][row][co], A + (aRow0 + row) * K + kb * 32 + co);
        }
        constexpr int BV = BN / 8;
        #pragma unroll
        for (int i = tid; i < 32 * BV; i += 256) {
            int row = i / BV, co = (i % BV) * 8;
            const __half* src;
            if (MODE == 3)
                src = B + (size_t)(kb * 32 + row) * G3 + u * BN + co;
            else
                src = B + ((size_t)u * UNITS + kb * 32 + row) * BN + co;
            cpa16(&sm.u.s.Bs[st][row][co], src);
        }
        asm volatile("cp.async.commit_group;");
    };

    const int warp = tid >> 5;
    const int wm = (warp / WNG) * (16 * FM);
    const int wn = (warp % WNG) * 48;

    wmma::fragment<wmma::accumulator, 16, 16, 16, float> acc[FM][FN];
    #pragma unroll
    for (int i = 0; i < FM; i++)
        #pragma unroll
        for (int j = 0; j < FN; j++)
            wmma::fill_fragment(acc[i][j], 0.f);

    // prologue: stages 0..2 in flight
    loadStage(0, 0);
    loadStage(1, 1);
    loadStage(2, 2);

    for (int kb = 0; kb < NK; kb++) {
        const int cur = kb & (N_STAGE - 1);
        // invariant: pending groups = {kb, kb+1, kb+2}; complete group kb
        asm volatile("cp.async.wait_group 2;");
        __syncthreads();
        if (kb + 3 < NK) loadStage((kb + 3) & (N_STAGE - 1), kb + 3);
        else             asm volatile("cp.async.commit_group;");  // keep count

        #pragma unroll
        for (int kk = 0; kk < 32; kk += 16) {
            wmma::fragment<wmma::matrix_a, 16, 16, 16, __half, wmma::row_major> af[FM];
            wmma::fragment<wmma::matrix_b, 16, 16, 16, __half, wmma::row_major> bf[FN];
            #pragma unroll
            for (int i = 0; i < FM; i++)
                wmma::load_matrix_sync(af[i], &sm.u.s.As[cur][wm + 16 * i][kk], 40);
            #pragma unroll
            for (int j = 0; j < FN; j++)
                wmma::load_matrix_sync(bf[j], &sm.u.s.Bs[cur][kk][wn + 16 * j], BN + 8);
            #pragma unroll
            for (int i = 0; i < FM; i++)
                #pragma unroll
                for (int j = 0; j < FN; j++)
                    wmma::mma_sync(acc[i][j], af[i], bf[j], acc[i][j]);
        }
    }

#if __CUDA_ARCH__ >= 900
    if (MODE == 0 || MODE == 2) cudaTriggerProgrammaticLaunchCompletion();
#endif

    asm volatile("cp.async.wait_group 0;");
    __syncthreads();   // all reads of As/Bs done; Cs (union) may be written

    #pragma unroll
    for (int i = 0; i < FM; i++)
        #pragma unroll
        for (int j = 0; j < FN; j++)
            wmma::store_matrix_sync(&sm.u.Cs[wm + 16 * i][wn + 16 * j],
                                    acc[i][j], BN, wmma::mem_row_major);
    __syncthreads();

    if ((MODE == 0 && z == 0) || MODE == 2) {
        for (int e = tid; e < 128 * BNU; e += 256) {
            int b = e / BNU, c = e % BNU;
            int j = u * BNU + c;
            float az = sm.u.Cs[b][c];
            float ar = sm.u.Cs[b][BNU + c];
            float ah = sm.u.Cs[b][2 * BNU + c];
            float giz, gir, gih, ghz, ghr, ghh;
            if (MODE == 0) {
                giz = __half2float(gi[(size_t)b * G3 + j]);
                gir = __half2float(gi[(size_t)b * G3 + UNITS + j]);
                gih = __half2float(gi[(size_t)b * G3 + 2 * UNITS + j]);
                ghz = az; ghr = ar; ghh = ah;
            } else {
                giz = az; gir = ar; gih = ah;
                ghz = g_gh1[(size_t)b * G3 + j];
                ghr = g_gh1[(size_t)b * G3 + UNITS + j];
                ghh = g_gh1[(size_t)b * G3 + 2 * UNITS + j];
            }
            float zg = 1.f / (1.f + __expf(-(giz + bias[j] + ghz + bias[G3 + j])));
            float rg = 1.f / (1.f + __expf(-(gir + bias[UNITS + j] + ghr + bias[G3 + UNITS + j])));
            float cd = tanhf(gih + bias[2 * UNITS + j] + rg * (ghh + bias[G3 + 2 * UNITS + j]));
            float hp = hprev[(size_t)b * UNITS + j];
            float hn = zg * hp + (1.f - zg) * cd;
            hn_f[(size_t)b * UNITS + j] = hn;
            hn_h[(size_t)b * UNITS + j] = __float2half(hn);
        }
    } else if (MODE == 0) {          // z == 1: raw gh1 store
        for (int e = tid; e < 128 * BN; e += 256) {
            int b = e / BN, col = e % BN;
            int g = col / BNU, c = col % BNU;
            g_gh1[(size_t)b * G3 + g * UNITS + u * BNU + c] = sm.u.Cs[b][col];
        }
    } else {                         // MODE 3: natural fp16 store of gi0
        for (int e = tid; e < 128 * BN; e += 256) {
            int row = e / BN, col = e % BN;
            g_gi0h[((size_t)blockIdx.y * 128 + row) * G3 + u * BN + col] =
                __float2half(sm.u.Cs[row][col]);
        }
    }
}

// ---------------- head ----------------
__global__ void out_kernel(const float* __restrict__ wout, const float* __restrict__ bout,
                           float* __restrict__ out) {
    __shared__ float red[256];
    int b = blockIdx.x, tid = threadIdx.x;
    float s = 0.f;
    for (int j = tid; j < UNITS; j += 256)
        s += g_h1f[0][(size_t)b * UNITS + j] * wout[j];
    red[tid] = s; __syncthreads();
    for (int off = 128; off > 0; off >>= 1) {
        if (tid < off) red[tid] += red[tid + off];
        __syncthreads();
    }
    if (tid == 0) out[b] = 1.f / (1.f + expf(-(red[0] + bout[0])));
}

// ---------------- launch ----------------
static int smem_sz(int mode) {
    return (mode == 2) ? (int)sizeof(SmemT<48>) : (int)sizeof(SmemT<96>);
}

template<int MODE>
static void launch_step(dim3 grid, int t, int p, const float* bias) {
    cudaLaunchConfig_t cfg = {};
    cfg.gridDim = grid;
    cfg.blockDim = dim3(256, 1, 1);
    cfg.dynamicSmemBytes = smem_sz(MODE);
    cfg.stream = 0;
    cudaLaunchAttribute at[1];
    at[0].id = cudaLaunchAttributeProgrammaticStreamSerialization;
    at[0].val.programmaticStreamSerializationAllowed = 1;
    cfg.attrs = at;
    cfg.numAttrs = 1;
    cudaLaunchKernelEx(&cfg, gk<MODE>, t, p, bias);
}

extern "C" void kernel_launch(void* const* d_in, const int* in_sizes, int n_in,
                              void* d_out, int out_size) {
    const int*   tokens = (const int*)  d_in[0];
    const float* emb    = (const float*)d_in[1];
    const float* k0     = (const float*)d_in[2];
    const float* r0     = (const float*)d_in[3];
    const float* b0     = (const float*)d_in[4];
    const float* k1     = (const float*)d_in[5];
    const float* r1     = (const float*)d_in[6];
    const float* b1     = (const float*)d_in[7];
    const float* wout   = (const float*)d_in[8];
    const float* bout   = (const float*)d_in[9];
    float* out = (float*)d_out;

    static int smem_set = 0;
    if (!smem_set) {
        cudaFuncSetAttribute(gk<0>, cudaFuncAttributeMaxDynamicSharedMemorySize, smem_sz(0));
        cudaFuncSetAttribute(gk<2>, cudaFuncAttributeMaxDynamicSharedMemorySize, smem_sz(2));
        cudaFuncSetAttribute(gk<3>, cudaFuncAttributeMaxDynamicSharedMemorySize, smem_sz(3));
        smem_set = 1;
    }

    const int PK = (UNITS * G3 + 255) / 256;
    pad_k0h     <<<(KPAD * G3 + 255) / 256, 256>>>(k0);
    gather_embed<<<(T_SEQ * BATCH * KPAD + 255) / 256, 256>>>(tokens, emb);
    pack_gates<32><<<PK, 256>>>(r0, 0);
    pack_gates<32><<<PK, 256>>>(r1, 1);
    pack_gates<16><<<PK, 256>>>(k1, 0);
    zero_h      <<<(BATCH * UNITS + 255) / 256, 256>>>();

    // all-timestep input projection gi0 = x @ k0
    gk<3><<<dim3(G3 / 96, T_SEQ, 1), 256, smem_sz(3)>>>(0, 0, nullptr);

    for (int t = 0; t < T_SEQ; t++) {
        int p = t & 1;
        launch_step<0>(dim3(UNITS / 32, 1, 2), t, p, b0);  // gh0+combine(h0) || gh1 raw
        launch_step<2>(dim3(UNITS / 16, 1, 1), t, p, b1);  // gi1+combine(h1)
    }

    out_kernel<<<BATCH, 256>>>(wout, bout, out);
}

// round 7
// speedup vs baseline: 1.5036x; 1.5036x over previous
#include <cuda_runtime.h>
#include <cuda_fp16.h>
#include <mma.h>
#include <math.h>

using namespace nvcuda;

#define T_SEQ 80
#define BATCH 128
#define EMB   100
#define KPAD  128
#define UNITS 2048
#define G3    6144

// ---------------- device scratch (allocation-free) ----------------
__device__ __half g_Bp0[(size_t)UNITS * G3];          // r0 packed [64][2048][96]
__device__ __half g_Bp1[(size_t)UNITS * G3];          // r1 packed [64][2048][96]
__device__ __half g_Bp2[(size_t)UNITS * G3];          // k1 packed [128][2048][48]
__device__ __half g_k0h[(size_t)KPAD * G3];           // k0 fp16, K padded to 128
__device__ __half g_xh [(size_t)T_SEQ * BATCH * KPAD];// gathered embeddings fp16
__device__ __half g_gi0h[(size_t)T_SEQ * BATCH * G3]; // precomputed input proj, fp16
__device__ float  g_gh1[(size_t)BATCH * G3];          // raw h1_prev @ r1 per step
__device__ float  g_h0f[2][(size_t)BATCH * UNITS];
__device__ float  g_h1f[2][(size_t)BATCH * UNITS];
__device__ __half g_h0h[2][(size_t)BATCH * UNITS];
__device__ __half g_h1h[2][(size_t)BATCH * UNITS];

// ---------------- prep kernels ----------------
__global__ void pad_k0h(const float* __restrict__ k0) {
    int idx = blockIdx.x * blockDim.x + threadIdx.x;
    if (idx >= KPAD * G3) return;
    int k = idx / G3;
    g_k0h[idx] = (k < EMB) ? __float2half(k0[idx]) : __half(0);
}

__global__ void gather_embed(const int* __restrict__ tokens, const float* __restrict__ emb) {
    int idx = blockIdx.x * blockDim.x + threadIdx.x;
    if (idx >= T_SEQ * BATCH * KPAD) return;
    int e  = idx & (KPAD - 1);
    int tb = idx >> 7;
    int t  = tb >> 7;          // BATCH == 128
    int b  = tb & 127;
    float v = 0.f;
    if (e < EMB) {
        int tok = tokens[b * T_SEQ + t];
        v = emb[(size_t)tok * EMB + e];
    }
    g_xh[idx] = __float2half(v);
}

// gate-interleave pack: out[u][k][g*BNU+c] = W[k][g*2048 + u*BNU + c]
template<int BNU>
__global__ void pack_gates(const float* __restrict__ W, int which) {
    __half* out = (BNU == 16) ? g_Bp2 : (which ? g_Bp1 : g_Bp0);
    int idx = blockIdx.x * blockDim.x + threadIdx.x;
    if (idx >= UNITS * G3) return;
    const int BNW = 3 * BNU;
    int u   = idx / (UNITS * BNW);
    int r   = idx % (UNITS * BNW);
    int k   = r / BNW;
    int col = r % BNW;
    int g   = col / BNU, c = col % BNU;
    out[idx] = __float2half(W[(size_t)k * G3 + g * UNITS + u * BNU + c]);
}

__global__ void zero_h() {
    int idx = blockIdx.x * blockDim.x + threadIdx.x;
    if (idx >= BATCH * UNITS) return;
    g_h0f[0][idx] = 0.f; g_h1f[0][idx] = 0.f;
    g_h0h[0][idx] = __half(0); g_h1h[0][idx] = __half(0);
}

// ---------------- fused fp16 tensor-core GEMM ----------------
// MODE 0: z=0: gh0 = h0@r0 fused layer-0 combine -> h0' ; z=1: gh1 = h1@r1 raw
// MODE 2: gi1 = h0'@k1 fused layer-1 combine -> h1'
// MODE 3: gi0 = x@k0 for all timesteps (one-time)

__device__ __forceinline__ void cpa16(void* s, const void* g) {
    unsigned sa = (unsigned)__cvta_generic_to_shared(s);
    asm volatile("cp.async.cg.shared.global [%0], [%1], 16;" :: "r"(sa), "l"(g));
}

#define N_STAGE 4

template<int BN> struct SmemT {
    union {
        struct { __half As[N_STAGE][128][40]; __half Bs[N_STAGE][32][BN + 8]; } s;
        float Cs[128][BN];
    } u;
};

template<int MODE>
__global__ __launch_bounds__(256)
void gk(int t, int p, const float* __restrict__ bias) {
    constexpr int BN  = (MODE == 2) ? 48 : 96;
    constexpr int BNU = BN / 3;
    constexpr int K   = (MODE == 3) ? KPAD : UNITS;
    constexpr int NK  = K / 32;
    constexpr int WNG = (BN == 96) ? 2 : 1;
    constexpr int FM  = (BN == 96) ? 2 : 1;
    constexpr int FN  = 3;

    const int u = blockIdx.x;
    const int z = (MODE == 0) ? blockIdx.z : 0;

    const __half* A;
    const __half* B;
    const __half* gi = g_gi0h + (size_t)t * BATCH * G3;
    const float*  hprev;
    float*  hn_f = nullptr;
    __half* hn_h = nullptr;

    if (MODE == 0) {
        A = z ? g_h1h[p] : g_h0h[p];
        B = z ? g_Bp1 : g_Bp0;
        hprev = g_h0f[p]; hn_f = g_h0f[p ^ 1]; hn_h = g_h0h[p ^ 1];
    } else if (MODE == 2) {
        A = g_h0h[p ^ 1];
        B = g_Bp2;
        hprev = g_h1f[p]; hn_f = g_h1f[p ^ 1]; hn_h = g_h1h[p ^ 1];
    } else {
        A = g_xh; B = g_k0h; hprev = nullptr;
    }

    extern __shared__ char smraw[];
    SmemT<BN>& sm = *reinterpret_cast<SmemT<BN>*>(smraw);

    const int tid = threadIdx.x;
    const size_t aRow0 = (MODE == 3) ? (size_t)blockIdx.y * 128 : 0;

    auto loadStage = [&](int st, int kb) {
        #pragma unroll
        for (int r = 0; r < 2; r++) {
            int i = tid + r * 256;
            int row = i >> 2, co = (i & 3) * 8;
            cpa16(&sm.u.s.As[st][row][co], A + (aRow0 + row) * K + kb * 32 + co);
        }
        constexpr int BV = BN / 8;
        #pragma unroll
        for (int i = tid; i < 32 * BV; i += 256) {
            int row = i / BV, co = (i % BV) * 8;
            const __half* src;
            if (MODE == 3)
                src = B + (size_t)(kb * 32 + row) * G3 + u * BN + co;
            else
                src = B + ((size_t)u * UNITS + kb * 32 + row) * BN + co;
            cpa16(&sm.u.s.Bs[st][row][co], src);
        }
        asm volatile("cp.async.commit_group;");
    };

    const int warp = tid >> 5;
    const int wm = (warp / WNG) * (16 * FM);
    const int wn = (warp % WNG) * 48;

    wmma::fragment<wmma::accumulator, 16, 16, 16, float> acc[FM][FN];
    #pragma unroll
    for (int i = 0; i < FM; i++)
        #pragma unroll
        for (int j = 0; j < FN; j++)
            wmma::fill_fragment(acc[i][j], 0.f);

    // prologue: stages 0..2 in flight
    loadStage(0, 0);
    loadStage(1, 1);
    loadStage(2, 2);

    for (int kb = 0; kb < NK; kb++) {
        const int cur = kb & (N_STAGE - 1);
        // invariant: pending groups = {kb, kb+1, kb+2}; complete group kb
        asm volatile("cp.async.wait_group 2;");
        __syncthreads();
        if (kb + 3 < NK) loadStage((kb + 3) & (N_STAGE - 1), kb + 3);
        else             asm volatile("cp.async.commit_group;");  // keep count

        #pragma unroll
        for (int kk = 0; kk < 32; kk += 16) {
            wmma::fragment<wmma::matrix_a, 16, 16, 16, __half, wmma::row_major> af[FM];
            wmma::fragment<wmma::matrix_b, 16, 16, 16, __half, wmma::row_major> bf[FN];
            #pragma unroll
            for (int i = 0; i < FM; i++)
                wmma::load_matrix_sync(af[i], &sm.u.s.As[cur][wm + 16 * i][kk], 40);
            #pragma unroll
            for (int j = 0; j < FN; j++)
                wmma::load_matrix_sync(bf[j], &sm.u.s.Bs[cur][kk][wn + 16 * j], BN + 8);
            #pragma unroll
            for (int i = 0; i < FM; i++)
                #pragma unroll
                for (int j = 0; j < FN; j++)
                    wmma::mma_sync(acc[i][j], af[i], bf[j], acc[i][j]);
        }
    }

    asm volatile("cp.async.wait_group 0;");
    __syncthreads();   // all reads of As/Bs done; Cs (union) may be written

    #pragma unroll
    for (int i = 0; i < FM; i++)
        #pragma unroll
        for (int j = 0; j < FN; j++)
            wmma::store_matrix_sync(&sm.u.Cs[wm + 16 * i][wn + 16 * j],
                                    acc[i][j], BN, wmma::mem_row_major);
    __syncthreads();

    if ((MODE == 0 && z == 0) || MODE == 2) {
        for (int e = tid; e < 128 * BNU; e += 256) {
            int b = e / BNU, c = e % BNU;
            int j = u * BNU + c;
            float az = sm.u.Cs[b][c];
            float ar = sm.u.Cs[b][BNU + c];
            float ah = sm.u.Cs[b][2 * BNU + c];
            float giz, gir, gih, ghz, ghr, ghh;
            if (MODE == 0) {
                giz = __half2float(gi[(size_t)b * G3 + j]);
                gir = __half2float(gi[(size_t)b * G3 + UNITS + j]);
                gih = __half2float(gi[(size_t)b * G3 + 2 * UNITS + j]);
                ghz = az; ghr = ar; ghh = ah;
            } else {
                giz = az; gir = ar; gih = ah;
                ghz = g_gh1[(size_t)b * G3 + j];
                ghr = g_gh1[(size_t)b * G3 + UNITS + j];
                ghh = g_gh1[(size_t)b * G3 + 2 * UNITS + j];
            }
            float zg = 1.f / (1.f + __expf(-(giz + bias[j] + ghz + bias[G3 + j])));
            float rg = 1.f / (1.f + __expf(-(gir + bias[UNITS + j] + ghr + bias[G3 + UNITS + j])));
            float cd = tanhf(gih + bias[2 * UNITS + j] + rg * (ghh + bias[G3 + 2 * UNITS + j]));
            float hp = hprev[(size_t)b * UNITS + j];
            float hn = zg * hp + (1.f - zg) * cd;
            hn_f[(size_t)b * UNITS + j] = hn;
            hn_h[(size_t)b * UNITS + j] = __float2half(hn);
        }
    } else if (MODE == 0) {          // z == 1: raw gh1 store
        for (int e = tid; e < 128 * BN; e += 256) {
            int b = e / BN, col = e % BN;
            int g = col / BNU, c = col % BNU;
            g_gh1[(size_t)b * G3 + g * UNITS + u * BNU + c] = sm.u.Cs[b][col];
        }
    } else {                         // MODE 3: natural fp16 store of gi0
        for (int e = tid; e < 128 * BN; e += 256) {
            int row = e / BN, col = e % BN;
            g_gi0h[((size_t)blockIdx.y * 128 + row) * G3 + u * BN + col] =
                __float2half(sm.u.Cs[row][col]);
        }
    }
}

// ---------------- head ----------------
__global__ void out_kernel(const float* __restrict__ wout, const float* __restrict__ bout,
                           float* __restrict__ out) {
    __shared__ float red[256];
    int b = blockIdx.x, tid = threadIdx.x;
    float s = 0.f;
    for (int j = tid; j < UNITS; j += 256)
        s += g_h1f[0][(size_t)b * UNITS + j] * wout[j];
    red[tid] = s; __syncthreads();
    for (int off = 128; off > 0; off >>= 1) {
        if (tid < off) red[tid] += red[tid + off];
        __syncthreads();
    }
    if (tid == 0) out[b] = 1.f / (1.f + expf(-(red[0] + bout[0])));
}

// ---------------- launch ----------------
static int smem_sz(int mode) {
    return (mode == 2) ? (int)sizeof(SmemT<48>) : (int)sizeof(SmemT<96>);
}

extern "C" void kernel_launch(void* const* d_in, const int* in_sizes, int n_in,
                              void* d_out, int out_size) {
    const int*   tokens = (const int*)  d_in[0];
    const float* emb    = (const float*)d_in[1];
    const float* k0     = (const float*)d_in[2];
    const float* r0     = (const float*)d_in[3];
    const float* b0     = (const float*)d_in[4];
    const float* k1     = (const float*)d_in[5];
    const float* r1     = (const float*)d_in[6];
    const float* b1     = (const float*)d_in[7];
    const float* wout   = (const float*)d_in[8];
    const float* bout   = (const float*)d_in[9];
    float* out = (float*)d_out;

    cudaFuncSetAttribute(gk<0>, cudaFuncAttributeMaxDynamicSharedMemorySize, smem_sz(0));
    cudaFuncSetAttribute(gk<2>, cudaFuncAttributeMaxDynamicSharedMemorySize, smem_sz(2));
    cudaFuncSetAttribute(gk<3>, cudaFuncAttributeMaxDynamicSharedMemorySize, smem_sz(3));

    const int PK = (UNITS * G3 + 255) / 256;
    pad_k0h     <<<(KPAD * G3 + 255) / 256, 256>>>(k0);
    gather_embed<<<(T_SEQ * BATCH * KPAD + 255) / 256, 256>>>(tokens, emb);
    pack_gates<32><<<PK, 256>>>(r0, 0);
    pack_gates<32><<<PK, 256>>>(r1, 1);
    pack_gates<16><<<PK, 256>>>(k1, 0);
    zero_h      <<<(BATCH * UNITS + 255) / 256, 256>>>();

    // all-timestep input projection gi0 = x @ k0
    gk<3><<<dim3(G3 / 96, T_SEQ, 1), 256, smem_sz(3)>>>(0, 0, nullptr);

    for (int t = 0; t < T_SEQ; t++) {
        int p = t & 1;
        gk<0><<<dim3(UNITS / 32, 1, 2), 256, smem_sz(0)>>>(t, p, b0);  // gh0+combine || gh1 raw
        gk<2><<<dim3(UNITS / 16, 1, 1), 256, smem_sz(2)>>>(t, p, b1);  // gi1+combine(h1)
    }

    out_kernel<<<BATCH, 256>>>(wout, bout, out);
}

// round 10
// speedup vs baseline: 1.6098x; 1.0706x over previous
#include <cuda_runtime.h>
#include <cuda_fp16.h>
#include <mma.h>
#include <math.h>

using namespace nvcuda;

#define T_SEQ 80
#define BATCH 128
#define EMB   100
#define KPAD  128
#define UNITS 2048
#define G3    6144

// ---------------- device scratch (allocation-free) ----------------
__device__ __half g_Bp0[(size_t)UNITS * G3];          // r0 packed [64 u][2048 k][96 col]
__device__ __half g_Bp1[(size_t)UNITS * G3];          // r1 packed [64 u][2048 k][96 col]
__device__ __half g_Bp2[(size_t)UNITS * G3];          // k1 packed [128 u][2048 k][48 col]
__device__ __half g_k0h[(size_t)KPAD * G3];           // k0 fp16, K padded to 128
__device__ __half g_xh [(size_t)T_SEQ * BATCH * KPAD];// gathered embeddings fp16
__device__ __half g_gi0h[(size_t)T_SEQ * BATCH * G3]; // precomputed input proj, fp16
__device__ float  g_gh1[(size_t)BATCH * G3];          // raw h1_prev @ r1 per step
__device__ float  g_h0f[2][(size_t)BATCH * UNITS];
__device__ float  g_h1f[2][(size_t)BATCH * UNITS];
__device__ __half g_h0h[2][(size_t)BATCH * UNITS];
__device__ __half g_h1h[2][(size_t)BATCH * UNITS];

// ---------------- prep kernels ----------------
__global__ void pad_k0h(const float* __restrict__ k0) {
    int idx = blockIdx.x * blockDim.x + threadIdx.x;
    if (idx >= KPAD * G3) return;
    int k = idx / G3;
    g_k0h[idx] = (k < EMB) ? __float2half(k0[idx]) : __half(0);
}

__global__ void gather_embed(const int* __restrict__ tokens, const float* __restrict__ emb) {
    int idx = blockIdx.x * blockDim.x + threadIdx.x;
    if (idx >= T_SEQ * BATCH * KPAD) return;
    int e  = idx & (KPAD - 1);
    int tb = idx >> 7;
    int t  = tb >> 7;          // BATCH == 128
    int b  = tb & 127;
    float v = 0.f;
    if (e < EMB) {
        int tok = tokens[b * T_SEQ + t];
        v = emb[(size_t)tok * EMB + e];
    }
    g_xh[idx] = __float2half(v);
}

// gate-interleave pack: out[u][k][g*BNU+c] = W[k][g*2048 + u*BNU + c]
template<int BNU>
__global__ void pack_gates(const float* __restrict__ W, int which) {
    __half* out = (BNU == 16) ? g_Bp2 : (which ? g_Bp1 : g_Bp0);
    int idx = blockIdx.x * blockDim.x + threadIdx.x;
    if (idx >= UNITS * G3) return;
    const int BNW = 3 * BNU;
    int u   = idx / (UNITS * BNW);
    int r   = idx % (UNITS * BNW);
    int k   = r / BNW;
    int col = r % BNW;
    int g   = col / BNU, c = col % BNU;
    out[idx] = __float2half(W[(size_t)k * G3 + g * UNITS + u * BNU + c]);
}

__global__ void zero_h() {
    int idx = blockIdx.x * blockDim.x + threadIdx.x;
    if (idx >= BATCH * UNITS) return;
    g_h0f[0][idx] = 0.f; g_h1f[0][idx] = 0.f;
    g_h0h[0][idx] = __half(0); g_h1h[0][idx] = __half(0);
}

// ---------------- fused fp16 tensor-core GEMM (K-chunk 64) ----------------
// MODE 0: z=0: gh0 = h0@r0 fused layer-0 combine -> h0' ; z=1: gh1 = h1@r1 raw
// MODE 2: gi1 = h0'@k1 fused layer-1 combine -> h1'
// MODE 3: gi0 = x@k0 for all timesteps (one-time)

__device__ __forceinline__ void cpa16(void* s, const void* g) {
    unsigned sa = (unsigned)__cvta_generic_to_shared(s);
    asm volatile("cp.async.cg.shared.global [%0], [%1], 16;" :: "r"(sa), "l"(g));
}

#define N_STAGE 4

template<int BN> struct SmemT {
    union {
        struct { __half As[N_STAGE][128][72]; __half Bs[N_STAGE][64][BN + 8]; } s;
        float Cs[128][BN];
    } u;
};

template<int MODE>
__global__ __launch_bounds__(256)
void gk(int t, int p, const float* __restrict__ bias) {
    constexpr int BN  = (MODE == 2) ? 48 : 96;
    constexpr int BNU = BN / 3;
    constexpr int K   = (MODE == 3) ? KPAD : UNITS;
    constexpr int NK  = K / 64;                // 32 step / 2 gi0
    constexpr int WNG = (BN == 96) ? 2 : 1;
    constexpr int FM  = (BN == 96) ? 2 : 1;
    constexpr int FN  = 3;

    const int u = blockIdx.x;
    const int z = (MODE == 0) ? blockIdx.z : 0;

    const __half* A;
    const __half* B;
    const __half* gi = g_gi0h + (size_t)t * BATCH * G3;
    const float*  hprev;
    float*  hn_f = nullptr;
    __half* hn_h = nullptr;

    if (MODE == 0) {
        A = z ? g_h1h[p] : g_h0h[p];
        B = z ? g_Bp1 : g_Bp0;
        hprev = g_h0f[p]; hn_f = g_h0f[p ^ 1]; hn_h = g_h0h[p ^ 1];
    } else if (MODE == 2) {
        A = g_h0h[p ^ 1];
        B = g_Bp2;
        hprev = g_h1f[p]; hn_f = g_h1f[p ^ 1]; hn_h = g_h1h[p ^ 1];
    } else {
        A = g_xh; B = g_k0h; hprev = nullptr;
    }

    extern __shared__ char smraw[];
    SmemT<BN>& sm = *reinterpret_cast<SmemT<BN>*>(smraw);

    const int tid = threadIdx.x;
    const size_t aRow0 = (MODE == 3) ? (size_t)blockIdx.y * 128 : 0;

    auto loadStage = [&](int st, int kb) {
        // A: 128 rows x 64 halves = 1024 x 16B chunks, 4 per thread
        #pragma unroll
        for (int r = 0; r < 4; r++) {
            int i = tid + r * 256;
            int row = i >> 3, c8 = (i & 7) * 8;
            cpa16(&sm.u.s.As[st][row][c8], A + (aRow0 + row) * K + kb * 64 + c8);
        }
        // B: 64 rows x BN halves
        constexpr int BV = BN / 8;        // 12 or 6
        #pragma unroll
        for (int i = tid; i < 64 * BV; i += 256) {
            int row = i / BV, c8 = (i % BV) * 8;
            const __half* src;
            if (MODE == 3)
                src = B + (size_t)(kb * 64 + row) * G3 + u * BN + c8;
            else
                src = B + ((size_t)u * UNITS + kb * 64 + row) * BN + c8;
            cpa16(&sm.u.s.Bs[st][row][c8], src);
        }
        asm volatile("cp.async.commit_group;");
    };

    const int warp = tid >> 5;
    const int wm = (warp / WNG) * (16 * FM);
    const int wn = (warp % WNG) * 48;

    wmma::fragment<wmma::accumulator, 16, 16, 16, float> acc[FM][FN];
    #pragma unroll
    for (int i = 0; i < FM; i++)
        #pragma unroll
        for (int j = 0; j < FN; j++)
            wmma::fill_fragment(acc[i][j], 0.f);

    // prologue: up to 3 stages in flight (guarded for small NK)
    #pragma unroll
    for (int s = 0; s < 3; s++) {
        if (s < NK) loadStage(s, s);
        else        asm volatile("cp.async.commit_group;");
    }

    for (int kb = 0; kb < NK; kb++) {
        const int cur = kb & (N_STAGE - 1);
        // invariant: 3 groups pending; complete group kb
        asm volatile("cp.async.wait_group 2;");
        __syncthreads();
        if (kb + 3 < NK) loadStage((kb + 3) & (N_STAGE - 1), kb + 3);
        else             asm volatile("cp.async.commit_group;");  // keep count

        #pragma unroll
        for (int kk = 0; kk < 64; kk += 16) {
            wmma::fragment<wmma::matrix_a, 16, 16, 16, __half, wmma::row_major> af[FM];
            wmma::fragment<wmma::matrix_b, 16, 16, 16, __half, wmma::row_major> bf[FN];
            #pragma unroll
            for (int i = 0; i < FM; i++)
                wmma::load_matrix_sync(af[i], &sm.u.s.As[cur][wm + 16 * i][kk], 72);
            #pragma unroll
            for (int j = 0; j < FN; j++)
                wmma::load_matrix_sync(bf[j], &sm.u.s.Bs[cur][kk][wn + 16 * j], BN + 8);
            #pragma unroll
            for (int i = 0; i < FM; i++)
                #pragma unroll
                for (int j = 0; j < FN; j++)
                    wmma::mma_sync(acc[i][j], af[i], bf[j], acc[i][j]);
        }
    }

    asm volatile("cp.async.wait_group 0;");
    __syncthreads();   // all reads of As/Bs done; Cs (union) may be written

    #pragma unroll
    for (int i = 0; i < FM; i++)
        #pragma unroll
        for (int j = 0; j < FN; j++)
            wmma::store_matrix_sync(&sm.u.Cs[wm + 16 * i][wn + 16 * j],
                                    acc[i][j], BN, wmma::mem_row_major);
    __syncthreads();

    if ((MODE == 0 && z == 0) || MODE == 2) {
        for (int e = tid; e < 128 * BNU; e += 256) {
            int b = e / BNU, c = e % BNU;
            int j = u * BNU + c;
            float az = sm.u.Cs[b][c];
            float ar = sm.u.Cs[b][BNU + c];
            float ah = sm.u.Cs[b][2 * BNU + c];
            float giz, gir, gih, ghz, ghr, ghh;
            if (MODE == 0) {
                giz = __half2float(gi[(size_t)b * G3 + j]);
                gir = __half2float(gi[(size_t)b * G3 + UNITS + j]);
                gih = __half2float(gi[(size_t)b * G3 + 2 * UNITS + j]);
                ghz = az; ghr = ar; ghh = ah;
            } else {
                giz = az; gir = ar; gih = ah;
                ghz = g_gh1[(size_t)b * G3 + j];
                ghr = g_gh1[(size_t)b * G3 + UNITS + j];
                ghh = g_gh1[(size_t)b * G3 + 2 * UNITS + j];
            }
            float zg = 1.f / (1.f + __expf(-(giz + bias[j] + ghz + bias[G3 + j])));
            float rg = 1.f / (1.f + __expf(-(gir + bias[UNITS + j] + ghr + bias[G3 + UNITS + j])));
            float cd = tanhf(gih + bias[2 * UNITS + j] + rg * (ghh + bias[G3 + 2 * UNITS + j]));
            float hp = hprev[(size_t)b * UNITS + j];
            float hn = zg * hp + (1.f - zg) * cd;
            hn_f[(size_t)b * UNITS + j] = hn;
            hn_h[(size_t)b * UNITS + j] = __float2half(hn);
        }
    } else if (MODE == 0) {          // z == 1: raw gh1 store
        for (int e = tid; e < 128 * BN; e += 256) {
            int b = e / BN, col = e % BN;
            int g = col / BNU, c = col % BNU;
            g_gh1[(size_t)b * G3 + g * UNITS + u * BNU + c] = sm.u.Cs[b][col];
        }
    } else {                         // MODE 3: natural fp16 store of gi0
        for (int e = tid; e < 128 * BN; e += 256) {
            int row = e / BN, col = e % BN;
            g_gi0h[((size_t)blockIdx.y * 128 + row) * G3 + u * BN + col] =
                __float2half(sm.u.Cs[row][col]);
        }
    }
}

// ---------------- head ----------------
__global__ void out_kernel(const float* __restrict__ wout, const float* __restrict__ bout,
                           float* __restrict__ out) {
    __shared__ float red[256];
    int b = blockIdx.x, tid = threadIdx.x;
    float s = 0.f;
    for (int j = tid; j < UNITS; j += 256)
        s += g_h1f[0][(size_t)b * UNITS + j] * wout[j];
    red[tid] = s; __syncthreads();
    for (int off = 128; off > 0; off >>= 1) {
        if (tid < off) red[tid] += red[tid + off];
        __syncthreads();
    }
    if (tid == 0) out[b] = 1.f / (1.f + expf(-(red[0] + bout[0])));
}

// ---------------- launch ----------------
static int smem_sz(int mode) {
    return (mode == 2) ? (int)sizeof(SmemT<48>) : (int)sizeof(SmemT<96>);
}

extern "C" void kernel_launch(void* const* d_in, const int* in_sizes, int n_in,
                              void* d_out, int out_size) {
    const int*   tokens = (const int*)  d_in[0];
    const float* emb    = (const float*)d_in[1];
    const float* k0     = (const float*)d_in[2];
    const float* r0     = (const float*)d_in[3];
    const float* b0     = (const float*)d_in[4];
    const float* k1     = (const float*)d_in[5];
    const float* r1     = (const float*)d_in[6];
    const float* b1     = (const float*)d_in[7];
    const float* wout   = (const float*)d_in[8];
    const float* bout   = (const float*)d_in[9];
    float* out = (float*)d_out;

    cudaFuncSetAttribute(gk<0>, cudaFuncAttributeMaxDynamicSharedMemorySize, smem_sz(0));
    cudaFuncSetAttribute(gk<2>, cudaFuncAttributeMaxDynamicSharedMemorySize, smem_sz(2));
    cudaFuncSetAttribute(gk<3>, cudaFuncAttributeMaxDynamicSharedMemorySize, smem_sz(3));

    const int PK = (UNITS * G3 + 255) / 256;
    pad_k0h     <<<(KPAD * G3 + 255) / 256, 256>>>(k0);
    gather_embed<<<(T_SEQ * BATCH * KPAD + 255) / 256, 256>>>(tokens, emb);
    pack_gates<32><<<PK, 256>>>(r0, 0);
    pack_gates<32><<<PK, 256>>>(r1, 1);
    pack_gates<16><<<PK, 256>>>(k1, 0);
    zero_h      <<<(BATCH * UNITS + 255) / 256, 256>>>();

    // all-timestep input projection gi0 = x @ k0
    gk<3><<<dim3(G3 / 96, T_SEQ, 1), 256, smem_sz(3)>>>(0, 0, nullptr);

    for (int t = 0; t < T_SEQ; t++) {
        int p = t & 1;
        gk<0><<<dim3(UNITS / 32, 1, 2), 256, smem_sz(0)>>>(t, p, b0);  // gh0+combine || gh1
        gk<2><<<dim3(UNITS / 16, 1, 1), 256, smem_sz(2)>>>(t, p, b1);  // gi1+combine(h1)
    }

    out_kernel<<<BATCH, 256>>>(wout, bout, out);
}